// round 15
// baseline (speedup 1.0000x reference)
#include <cuda_runtime.h>
#include <cuda_fp16.h>

#define NN 100000
#define EE 1600000
#define DD 64
#define SCAN_BS 1024
#define SCAN_NB ((NN + SCAN_BS - 1) / SCAN_BS)   // 98

// ---- scratch (static device globals; no allocation anywhere) ----
// zeroed as one block each launch: [dr | dg | cnt]
__device__ float    g_zbuf[3 * NN];
__device__ int      g_rp[NN + 1];              // CSR row_ptr (by dst)
__device__ int      g_cur[NN];                 // scatter cursors
__device__ int      g_bsum[SCAN_NB];           // scan block sums
__device__ unsigned g_epk[EE];                 // CSR: (src<<15) | fp16(w) sans sign
__device__ __align__(16) __half g_hsh[NN * DD];   // fp16: dinv * (x@W1)
__device__ __align__(16) __half g_hsh2[NN * DD];  // fp16: dinv * (x2@W2)
__device__ float g_h3s[NN];

__device__ __forceinline__ float guard1(float v) { return v > 0.f ? v : 1.f; }

__device__ __forceinline__ unsigned f2tf32(float v) {
    unsigned t;
    asm("cvt.rna.tf32.f32 %0, %1;" : "=r"(t) : "f"(v));
    return t;
}

__device__ __forceinline__ void mma_tf32(float* d,
                                         unsigned a0, unsigned a1, unsigned a2, unsigned a3,
                                         unsigned b0, unsigned b1) {
    asm volatile(
        "mma.sync.aligned.m16n8k8.row.col.f32.tf32.tf32.f32 "
        "{%0,%1,%2,%3}, {%4,%5,%6,%7}, {%8,%9}, {%0,%1,%2,%3};"
        : "+f"(d[0]), "+f"(d[1]), "+f"(d[2]), "+f"(d[3])
        : "r"(a0), "r"(a1), "r"(a2), "r"(a3), "r"(b0), "r"(b1));
}

__device__ __forceinline__ void dec_epk(unsigned v, int& s, float& w) {
    s = (int)(v >> 15);
    w = __half2float(__ushort_as_half((unsigned short)(v & 0x7FFFu)));
}

// ---------------- precompute (exact R8 configuration) ----------------

__global__ void k_pre1(const int* __restrict__ src, const int* __restrict__ dst,
                       const float* __restrict__ ev,
                       float* __restrict__ dr, int* __restrict__ cnt, int E) {
    int e = blockIdx.x * blockDim.x + threadIdx.x;
    if (e >= E) return;
    atomicAdd(&dr[src[e]], ev[e]);
    atomicAdd(&cnt[dst[e]], 1);
}

__global__ void k_scan1(const int* __restrict__ cnt, int* __restrict__ rp,
                        int* __restrict__ bsum, int N) {
    __shared__ int ws[32];
    int t = threadIdx.x;
    int lane = t & 31, wid = t >> 5;
    int i = blockIdx.x * SCAN_BS + t;
    int v = (i < N) ? cnt[i] : 0;
    int x = v;
#pragma unroll
    for (int o = 1; o < 32; o <<= 1) {
        int y = __shfl_up_sync(0xffffffffu, x, o);
        if (lane >= o) x += y;
    }
    if (lane == 31) ws[wid] = x;
    __syncthreads();
    if (wid == 0) {
        int s = ws[lane];
#pragma unroll
        for (int o = 1; o < 32; o <<= 1) {
            int y = __shfl_up_sync(0xffffffffu, s, o);
            if (lane >= o) s += y;
        }
        ws[lane] = s;
    }
    __syncthreads();
    int incl = x + (wid ? ws[wid - 1] : 0);
    if (i < N) rp[i] = incl - v;
    if (t == SCAN_BS - 1) bsum[blockIdx.x] = incl;
}

__global__ void k_scan3(int* __restrict__ rp, int* __restrict__ cur,
                        const int* __restrict__ bsum, int N, int E) {
    __shared__ int sh[128];
    int t = threadIdx.x;
    if (t < 128) sh[t] = (t < SCAN_NB) ? bsum[t] : 0;
    __syncthreads();
#pragma unroll
    for (int o = 1; o < 128; o <<= 1) {
        int add = (t >= o && t < 128) ? sh[t - o] : 0;
        __syncthreads();
        if (t < 128) sh[t] += add;
        __syncthreads();
    }
    int i = blockIdx.x * blockDim.x + t;
    if (i >= N) return;
    int blk = i >> 10;
    int off = blk ? sh[blk - 1] : 0;
    int r = rp[i] + off;
    rp[i] = r;
    cur[i] = r;
    if (i == 0) rp[N] = E;
}

// fused: w_hat compute + deg accumulation + packed CSR scatter
__global__ void k_scatter(const int* __restrict__ src, const int* __restrict__ dst,
                          const float* __restrict__ ev, const float* __restrict__ dr,
                          float* __restrict__ dg, int* __restrict__ cur,
                          unsigned* __restrict__ epk, int E) {
    int e = blockIdx.x * blockDim.x + threadIdx.x;
    if (e >= E) return;
    int s = src[e], d = dst[e];
    float w = ev[e] / (guard1(__ldg(&dr[s])) * guard1(__ldg(&dr[d])));
    atomicAdd(&dg[d], w);
    int p = atomicAdd(&cur[d], 1);
    unsigned hb = (unsigned)__half_as_ushort(__float2half_rn(w));  // w>0: bit15=0
    epk[p] = ((unsigned)s << 15) | hb;
}

// ---------------- layers ----------------

#define XA 68   // xs stride: conflict-free A-frag loads
#define WB 72   // Ws stride: conflict-free B-frag loads

// Layer 1 GEMM: hsh[row,c] = half( (dv[row]/rowsum(feat[row])) * (feat@W1)[c] )
__global__ void k_gemm0(const float* __restrict__ in, const float* __restrict__ W,
                        const float* __restrict__ dg, __half* __restrict__ hsh, int N) {
    __shared__ float Ws[DD * WB];
    __shared__ float xs[DD * XA];
    __shared__ float scal[64];
    int tid = threadIdx.x;
    int row0 = blockIdx.x * 64;

#pragma unroll
    for (int it = 0; it < 16; it++) {
        int i = it * 256 + tid;
        Ws[(i >> 6) * WB + (i & 63)] = __uint_as_float(f2tf32(W[i]));
    }
#pragma unroll
    for (int it = 0; it < 16; it++) {
        int i = it * 256 + tid;
        int r = i >> 6, c = i & 63;
        int row = row0 + r;
        xs[r * XA + c] = (row < N) ? in[(size_t)row * DD + c] : 0.f;
    }
    __syncthreads();
    if (tid < 64) {
        int row = row0 + tid;
        float s = 0.f;
        const float* xr = &xs[tid * XA];
#pragma unroll
        for (int c = 0; c < DD; c++) s += xr[c];
        float dv = (row < N) ? rsqrtf(1.f + dg[row]) : 0.f;
        scal[tid] = dv / fmaxf(s, 1e-30f);
    }
    __syncthreads();
#pragma unroll
    for (int it = 0; it < 16; it++) {
        int i = it * 256 + tid;
        int r = i >> 6, c = i & 63;
        xs[r * XA + c] = __uint_as_float(f2tf32(xs[r * XA + c]));
    }
    __syncthreads();

    int warp = tid >> 5, lane = tid & 31;
    int m0 = (warp & 3) << 4;
    int n0 = (warp >> 2) << 5;
    int g = lane >> 2, tig = lane & 3;
    float acc[4][4];
#pragma unroll
    for (int s = 0; s < 4; s++) { acc[s][0] = acc[s][1] = acc[s][2] = acc[s][3] = 0.f; }
#pragma unroll
    for (int ks = 0; ks < 8; ks++) {
        int k0 = ks << 3;
        unsigned a0 = __float_as_uint(xs[(m0 + g)     * XA + k0 + tig]);
        unsigned a1 = __float_as_uint(xs[(m0 + g + 8) * XA + k0 + tig]);
        unsigned a2 = __float_as_uint(xs[(m0 + g)     * XA + k0 + tig + 4]);
        unsigned a3 = __float_as_uint(xs[(m0 + g + 8) * XA + k0 + tig + 4]);
#pragma unroll
        for (int sub = 0; sub < 4; sub++) {
            int n = n0 + (sub << 3) + g;
            unsigned b0 = __float_as_uint(Ws[(k0 + tig)     * WB + n]);
            unsigned b1 = __float_as_uint(Ws[(k0 + tig + 4) * WB + n]);
            mma_tf32(acc[sub], a0, a1, a2, a3, b0, b1);
        }
    }
    int rlo = m0 + g, rhi = m0 + g + 8;
    int row_lo = row0 + rlo, row_hi = row0 + rhi;
    float s0 = scal[rlo], s1 = scal[rhi];
#pragma unroll
    for (int sub = 0; sub < 4; sub++) {
        int col = n0 + (sub << 3) + (tig << 1);
        if (row_lo < N) {
            __half2 h = __floats2half2_rn(s0 * acc[sub][0], s0 * acc[sub][1]);
            *(__half2*)&hsh[(size_t)row_lo * DD + col] = h;
        }
        if (row_hi < N) {
            __half2 h = __floats2half2_rn(s1 * acc[sub][2], s1 * acc[sub][3]);
            *(__half2*)&hsh[(size_t)row_hi * DD + col] = h;
        }
    }
}

// Fused layer 2: per-row staged agg with DOUBLE-BUFFERED cross-row staging
// prefetch + fully unrolled gather loop; then relu(b1+dv*a), tf32 stage,
// mma with W2; out = half(dv * (x2@W2)).
__global__ void k_agg_gemm(const __half* __restrict__ hsh,
                           const int* __restrict__ rp, const unsigned* __restrict__ epk,
                           const float* __restrict__ W, const float* __restrict__ b,
                           const float* __restrict__ dg,
                           __half* __restrict__ out, int N) {
    __shared__ float Ws[DD * WB];
    __shared__ float xs[DD * XA];
    __shared__ float dvs[64];
    __shared__ unsigned st[8][2][32];   // double-buffered staging
    int tid = threadIdx.x;
    int warp = tid >> 5, lane = tid & 31;
    int row0 = blockIdx.x * 64;

#pragma unroll
    for (int it = 0; it < 16; it++) {
        int i = it * 256 + tid;
        Ws[(i >> 6) * WB + (i & 63)] = __uint_as_float(f2tf32(W[i]));
    }
    if (tid < 64) {
        int row = row0 + tid;
        dvs[tid] = (row < N) ? rsqrtf(1.f + dg[row]) : 0.f;
    }
    __syncthreads();

    int c2 = lane << 1;
    float bx = __ldg(&b[c2]), by = __ldg(&b[c2 + 1]);

    // prologue: stage first batch of this warp's row 0
    int warpRow = row0 + (warp << 3);
    int nbeg = 0, nend = 0;
    if (warpRow < N) { nbeg = rp[warpRow]; nend = rp[warpRow + 1]; }
    if (nbeg < nend) {
        int m0b = nend - nbeg; if (m0b > 32) m0b = 32;
        st[warp][0][lane] = __ldg(&epk[nbeg + ((lane < m0b) ? lane : (m0b - 1))]);
    }
    int buf = 0;
#pragma unroll
    for (int q = 0; q < 8; q++) {
        int r = (warp << 3) + q;
        int n = row0 + r;
        int beg = nbeg, end = nend;
        __syncwarp();
        // prefetch next row's first batch into the other buffer
        if (q < 7) {
            int n2 = n + 1;
            nbeg = 0; nend = 0;
            if (n2 < N) { nbeg = rp[n2]; nend = rp[n2 + 1]; }
            if (nbeg < nend) {
                int m2 = nend - nbeg; if (m2 > 32) m2 = 32;
                st[warp][buf ^ 1][lane] = __ldg(&epk[nbeg + ((lane < m2) ? lane : (m2 - 1))]);
            }
        }
        __syncwarp();
        float vx = 0.f, vy = 0.f;
        if (n < N) {
            float2 a = __half22float2(*(const __half2*)&hsh[(size_t)n * DD + c2]);
            int m = end - beg; if (m > 32) m = 32;
            if (m == 32) {
#pragma unroll
                for (int k = 0; k < 32; k++) {
                    int s; float w; dec_epk(st[warp][buf][k], s, w);
                    float2 hv = __half22float2(*(const __half2*)&hsh[(size_t)s * DD + c2]);
                    a.x += w * hv.x;
                    a.y += w * hv.y;
                }
            } else {
                for (int k = 0; k < m; k++) {
                    int s; float w; dec_epk(st[warp][buf][k], s, w);
                    float2 hv = __half22float2(*(const __half2*)&hsh[(size_t)s * DD + c2]);
                    a.x += w * hv.x;
                    a.y += w * hv.y;
                }
            }
            // overflow batches (deg > 32; rare at mean deg 16) — serial, reuse buf
            for (int j0 = beg + 32; j0 < end; j0 += 32) {
                __syncwarp();
                int mm = end - j0; if (mm > 32) mm = 32;
                st[warp][buf][lane] = __ldg(&epk[j0 + ((lane < mm) ? lane : (mm - 1))]);
                __syncwarp();
                if (mm == 32) {
#pragma unroll
                    for (int k = 0; k < 32; k++) {
                        int s; float w; dec_epk(st[warp][buf][k], s, w);
                        float2 hv = __half22float2(*(const __half2*)&hsh[(size_t)s * DD + c2]);
                        a.x += w * hv.x;
                        a.y += w * hv.y;
                    }
                } else {
                    for (int k = 0; k < mm; k++) {
                        int s; float w; dec_epk(st[warp][buf][k], s, w);
                        float2 hv = __half22float2(*(const __half2*)&hsh[(size_t)s * DD + c2]);
                        a.x += w * hv.x;
                        a.y += w * hv.y;
                    }
                }
            }
            float dn = dvs[r];
            vx = fmaxf(bx + dn * a.x, 0.f);
            vy = fmaxf(by + dn * a.y, 0.f);
        }
        xs[r * XA + c2]     = __uint_as_float(f2tf32(vx));
        xs[r * XA + c2 + 1] = __uint_as_float(f2tf32(vy));
        buf ^= 1;
    }
    __syncthreads();

    int m0 = (warp & 3) << 4;
    int nb0 = (warp >> 2) << 5;
    int g = lane >> 2, tig = lane & 3;
    float acc[4][4];
#pragma unroll
    for (int s = 0; s < 4; s++) { acc[s][0] = acc[s][1] = acc[s][2] = acc[s][3] = 0.f; }
#pragma unroll
    for (int ks = 0; ks < 8; ks++) {
        int k0 = ks << 3;
        unsigned a0 = __float_as_uint(xs[(m0 + g)     * XA + k0 + tig]);
        unsigned a1 = __float_as_uint(xs[(m0 + g + 8) * XA + k0 + tig]);
        unsigned a2 = __float_as_uint(xs[(m0 + g)     * XA + k0 + tig + 4]);
        unsigned a3 = __float_as_uint(xs[(m0 + g + 8) * XA + k0 + tig + 4]);
#pragma unroll
        for (int sub = 0; sub < 4; sub++) {
            int n = nb0 + (sub << 3) + g;
            unsigned b0 = __float_as_uint(Ws[(k0 + tig)     * WB + n]);
            unsigned b1 = __float_as_uint(Ws[(k0 + tig + 4) * WB + n]);
            mma_tf32(acc[sub], a0, a1, a2, a3, b0, b1);
        }
    }
    int rlo = m0 + g, rhi = m0 + g + 8;
    int row_lo = row0 + rlo, row_hi = row0 + rhi;
    float s0 = dvs[rlo], s1 = dvs[rhi];
#pragma unroll
    for (int sub = 0; sub < 4; sub++) {
        int col = nb0 + (sub << 3) + (tig << 1);
        if (row_lo < N) {
            __half2 h = __floats2half2_rn(s0 * acc[sub][0], s0 * acc[sub][1]);
            *(__half2*)&out[(size_t)row_lo * DD + col] = h;
        }
        if (row_hi < N) {
            __half2 h = __floats2half2_rn(s1 * acc[sub][2], s1 * acc[sub][3]);
            *(__half2*)&out[(size_t)row_hi * DD + col] = h;
        }
    }
}

// Fused layer 3 head (frozen R8 warp-per-node agg): aggregate from hsh2, then
// h3s[n] = dv[n] * ( relu(b2 + dv[n]*a) . W3 )
__global__ void k_agg_dot(const __half* __restrict__ hsh2,
                          const int* __restrict__ rp, const unsigned* __restrict__ epk,
                          const float* __restrict__ W3, const float* __restrict__ b2,
                          const float* __restrict__ dg,
                          float* __restrict__ h3s, int N) {
    __shared__ unsigned st[8][32];
    int wid  = threadIdx.x >> 5;
    int lane = threadIdx.x & 31;
    int n = (blockIdx.x * blockDim.x + threadIdx.x) >> 5;
    if (n >= N) return;
    int c2 = lane << 1;
    float2 a = __half22float2(*(const __half2*)&hsh2[(size_t)n * DD + c2]);
    int beg = rp[n], end = rp[n + 1];
    for (int j0 = beg; j0 < end; j0 += 32) {
        int m = end - j0;
        int jl = j0 + ((lane < m) ? lane : (m - 1));
        st[wid][lane] = __ldg(&epk[jl]);
        __syncwarp();
        if (m >= 32) {
#pragma unroll 8
            for (int k = 0; k < 32; k++) {
                int s; float w; dec_epk(st[wid][k], s, w);
                float2 hv = __half22float2(*(const __half2*)&hsh2[(size_t)s * DD + c2]);
                a.x += w * hv.x;
                a.y += w * hv.y;
            }
        } else {
            for (int k = 0; k < m; k++) {
                int s; float w; dec_epk(st[wid][k], s, w);
                float2 hv = __half22float2(*(const __half2*)&hsh2[(size_t)s * DD + c2]);
                a.x += w * hv.x;
                a.y += w * hv.y;
            }
        }
        __syncwarp();
    }
    float d = rsqrtf(1.f + __ldg(&dg[n]));
    float v0 = fmaxf(__ldg(&b2[c2])     + d * a.x, 0.f);
    float v1 = fmaxf(__ldg(&b2[c2 + 1]) + d * a.y, 0.f);
    float s = v0 * __ldg(&W3[c2]) + v1 * __ldg(&W3[c2 + 1]);
#pragma unroll
    for (int o = 16; o > 0; o >>= 1) s += __shfl_xor_sync(0xffffffffu, s, o);
    if (lane == 0) h3s[n] = d * s;
}

// out[n] = b3 + dv[n] * ( h3s[n] + sum w*h3s[src] )   (warp per node)
__global__ void k_agg3(const float* __restrict__ h3s, float* __restrict__ out,
                       const int* __restrict__ rp, const unsigned* __restrict__ epk,
                       const float* __restrict__ b3, const float* __restrict__ dg,
                       int N) {
    int n = (blockIdx.x * blockDim.x + threadIdx.x) >> 5;
    int lane = threadIdx.x & 31;
    if (n >= N) return;
    int beg = rp[n], end = rp[n + 1];
    float t = 0.f;
    for (int j = beg + lane; j < end; j += 32) {
        int s; float w; dec_epk(__ldg(&epk[j]), s, w);
        t += w * __ldg(&h3s[s]);
    }
#pragma unroll
    for (int o = 16; o > 0; o >>= 1) t += __shfl_xor_sync(0xffffffffu, t, o);
    if (lane == 0) {
        float d = rsqrtf(1.f + __ldg(&dg[n]));
        out[n] = __ldg(&b3[0]) + d * (h3s[n] + t);
    }
}

// ---------------- launch ----------------

extern "C" void kernel_launch(void* const* d_in, const int* in_sizes, int n_in,
                              void* d_out, int out_size) {
    const float* feat = (const float*)d_in[0];
    const int*   ei   = (const int*)d_in[1];   // int32 (JAX x64 disabled)
    const float* ev   = (const float*)d_in[2];
    const float* W1   = (const float*)d_in[3];
    const float* b1   = (const float*)d_in[4];
    const float* W2   = (const float*)d_in[5];
    const float* b2   = (const float*)d_in[6];
    const float* W3   = (const float*)d_in[7];
    const float* b3   = (const float*)d_in[8];
    float* out = (float*)d_out;

    int N = in_sizes[0] / DD;
    int E = in_sizes[2];
    const int* src = ei;
    const int* dst = ei + E;

    float *zbuf, *ph3s;
    __half *phsh, *phsh2;
    unsigned* epk;
    int *rp, *cur, *bsum;
    cudaGetSymbolAddress((void**)&zbuf,  g_zbuf);
    cudaGetSymbolAddress((void**)&rp,    g_rp);
    cudaGetSymbolAddress((void**)&cur,   g_cur);
    cudaGetSymbolAddress((void**)&bsum,  g_bsum);
    cudaGetSymbolAddress((void**)&epk,   g_epk);
    cudaGetSymbolAddress((void**)&phsh,  g_hsh);
    cudaGetSymbolAddress((void**)&phsh2, g_hsh2);
    cudaGetSymbolAddress((void**)&ph3s,  g_h3s);

    float* dr = zbuf;            // deg_row
    float* dg = zbuf + NN;       // deg (A_hat col sums into dst)
    int*   cnt = (int*)(zbuf + 2 * NN);

    int nb  = (N + 255) / 256;
    int ebl = (E + 255) / 256;
    int wnb = (N * 32 + 255) / 256;
    int gemm_blocks = (N + 63) / 64;

    // zero dr/dg/cnt in one memset node
    cudaMemsetAsync(zbuf, 0, 3 * NN * sizeof(float), 0);

    // CSR build (+deg fused into scatter) — exact R8 configuration
    k_pre1   <<<ebl, 256>>>(src, dst, ev, dr, cnt, E);
    k_scan1  <<<SCAN_NB, SCAN_BS>>>(cnt, rp, bsum, N);
    k_scan3  <<<nb, 256>>>(rp, cur, bsum, N, E);
    k_scatter<<<ebl, 256>>>(src, dst, ev, dr, dg, cur, epk, E);

    // layer 1: feat -> hsh (rowsum + dinv folded in-kernel)
    k_gemm0   <<<gemm_blocks, 256>>>(feat, W1, dg, phsh, N);
    // layer 2: fused pipelined agg(hsh) + relu(b1+dv*a) + GEMM(W2) -> hsh2
    k_agg_gemm<<<gemm_blocks, 256>>>(phsh, rp, epk, W2, b1, dg, phsh2, N);
    // layer 3 head: fused agg(hsh2) + relu(b2+dv*a).W3 -> h3s
    k_agg_dot <<<wnb, 256>>>(phsh2, rp, epk, W3, b2, dg, ph3s, N);
    // final aggregation
    k_agg3    <<<wnb, 256>>>(ph3s, out, rp, epk, b3, dg, N);
}

// round 16
// speedup vs baseline: 1.1370x; 1.1370x over previous
#include <cuda_runtime.h>
#include <cuda_fp16.h>

#define NN 100000
#define EE 1600000
#define DD 64
#define SCAN_BS 1024
#define SCAN_NB ((NN + SCAN_BS - 1) / SCAN_BS)   // 98

// ---- scratch (static device globals; no allocation anywhere) ----
// zeroed as one block each launch: [dr | dg | cnt]
__device__ float    g_zbuf[3 * NN];
__device__ int      g_rp[NN + 1];              // CSR row_ptr (by dst)
__device__ int      g_cur[NN];                 // scatter cursors
__device__ int      g_bsum[SCAN_NB];           // scan block sums
__device__ unsigned g_epk[EE];                 // CSR: (src<<15) | fp16(w) sans sign
__device__ __align__(16) __half g_hsh[NN * DD];   // fp16: dinv * (x@W1)
__device__ __align__(16) __half g_hsh2[NN * DD];  // fp16: dinv * (x2@W2)
__device__ float g_h3s[NN];

__device__ __forceinline__ float guard1(float v) { return v > 0.f ? v : 1.f; }

__device__ __forceinline__ unsigned f2tf32(float v) {
    unsigned t;
    asm("cvt.rna.tf32.f32 %0, %1;" : "=r"(t) : "f"(v));
    return t;
}

__device__ __forceinline__ void mma_tf32(float* d,
                                         unsigned a0, unsigned a1, unsigned a2, unsigned a3,
                                         unsigned b0, unsigned b1) {
    asm volatile(
        "mma.sync.aligned.m16n8k8.row.col.f32.tf32.tf32.f32 "
        "{%0,%1,%2,%3}, {%4,%5,%6,%7}, {%8,%9}, {%0,%1,%2,%3};"
        : "+f"(d[0]), "+f"(d[1]), "+f"(d[2]), "+f"(d[3])
        : "r"(a0), "r"(a1), "r"(a2), "r"(a3), "r"(b0), "r"(b1));
}

__device__ __forceinline__ void dec_epk(unsigned v, int& s, float& w) {
    s = (int)(v >> 15);
    w = __half2float(__ushort_as_half((unsigned short)(v & 0x7FFFu)));
}

// ---------------- precompute ----------------

__global__ void k_pre1(const int* __restrict__ src, const int* __restrict__ dst,
                       const float* __restrict__ ev,
                       float* __restrict__ dr, int* __restrict__ cnt, int E) {
    int e = blockIdx.x * blockDim.x + threadIdx.x;
    if (e >= E) return;
    atomicAdd(&dr[src[e]], ev[e]);
    atomicAdd(&cnt[dst[e]], 1);
}

// block-level exclusive scan of cnt -> rp ; block totals -> bsum (shfl-based)
__global__ void k_scan1(const int* __restrict__ cnt, int* __restrict__ rp,
                        int* __restrict__ bsum, int N) {
    __shared__ int ws[32];
    int t = threadIdx.x;
    int lane = t & 31, wid = t >> 5;
    int i = blockIdx.x * SCAN_BS + t;
    int v = (i < N) ? cnt[i] : 0;
    int x = v;
#pragma unroll
    for (int o = 1; o < 32; o <<= 1) {
        int y = __shfl_up_sync(0xffffffffu, x, o);
        if (lane >= o) x += y;
    }
    if (lane == 31) ws[wid] = x;
    __syncthreads();
    if (wid == 0) {
        int s = ws[lane];
#pragma unroll
        for (int o = 1; o < 32; o <<= 1) {
            int y = __shfl_up_sync(0xffffffffu, s, o);
            if (lane >= o) s += y;
        }
        ws[lane] = s;
    }
    __syncthreads();
    int incl = x + (wid ? ws[wid - 1] : 0);
    if (i < N) rp[i] = incl - v;
    if (t == SCAN_BS - 1) bsum[blockIdx.x] = incl;
}

// rp[i] += prefix(bsum) ; cursor = rp ; rp[N] = E (redundant per-block scan)
__global__ void k_scan3(int* __restrict__ rp, int* __restrict__ cur,
                        const int* __restrict__ bsum, int N, int E) {
    __shared__ int sh[128];
    int t = threadIdx.x;
    if (t < 128) sh[t] = (t < SCAN_NB) ? bsum[t] : 0;
    __syncthreads();
#pragma unroll
    for (int o = 1; o < 128; o <<= 1) {
        int add = (t >= o && t < 128) ? sh[t - o] : 0;
        __syncthreads();
        if (t < 128) sh[t] += add;
        __syncthreads();
    }
    int i = blockIdx.x * blockDim.x + t;
    if (i >= N) return;
    int blk = i >> 10;
    int off = blk ? sh[blk - 1] : 0;
    int r = rp[i] + off;
    rp[i] = r;
    cur[i] = r;
    if (i == 0) rp[N] = E;
}

// fused: w_hat compute + deg accumulation + packed CSR scatter
__global__ void k_scatter(const int* __restrict__ src, const int* __restrict__ dst,
                          const float* __restrict__ ev, const float* __restrict__ dr,
                          float* __restrict__ dg, int* __restrict__ cur,
                          unsigned* __restrict__ epk, int E) {
    int e = blockIdx.x * blockDim.x + threadIdx.x;
    if (e >= E) return;
    int s = src[e], d = dst[e];
    float w = ev[e] / (guard1(__ldg(&dr[s])) * guard1(__ldg(&dr[d])));
    atomicAdd(&dg[d], w);
    int p = atomicAdd(&cur[d], 1);
    unsigned hb = (unsigned)__half_as_ushort(__float2half_rn(w));  // w>0: bit15=0
    epk[p] = ((unsigned)s << 15) | hb;
}

// ---------------- layers ----------------

#define XA 68   // xs stride: conflict-free A-frag loads
#define WB 72   // Ws stride: conflict-free B-frag loads

// Layer 1 GEMM: hsh[row,c] = half( (dv[row]/rowsum(feat[row])) * (feat@W1)[c] )
__global__ void k_gemm0(const float* __restrict__ in, const float* __restrict__ W,
                        const float* __restrict__ dg, __half* __restrict__ hsh, int N) {
    __shared__ float Ws[DD * WB];
    __shared__ float xs[DD * XA];
    __shared__ float scal[64];
    int tid = threadIdx.x;
    int row0 = blockIdx.x * 64;

#pragma unroll
    for (int it = 0; it < 16; it++) {
        int i = it * 256 + tid;
        Ws[(i >> 6) * WB + (i & 63)] = __uint_as_float(f2tf32(W[i]));
    }
    // stage raw feat
#pragma unroll
    for (int it = 0; it < 16; it++) {
        int i = it * 256 + tid;
        int r = i >> 6, c = i & 63;
        int row = row0 + r;
        xs[r * XA + c] = (row < N) ? in[(size_t)row * DD + c] : 0.f;
    }
    __syncthreads();
    // per-row sums -> scal = dv/rowsum  (dv computed inline from dg)
    if (tid < 64) {
        int row = row0 + tid;
        float s = 0.f;
        const float* xr = &xs[tid * XA];
#pragma unroll
        for (int c = 0; c < DD; c++) s += xr[c];
        float dv = (row < N) ? rsqrtf(1.f + dg[row]) : 0.f;
        scal[tid] = dv / fmaxf(s, 1e-30f);
    }
    __syncthreads();
    // cvt staged tile to tf32 in place
#pragma unroll
    for (int it = 0; it < 16; it++) {
        int i = it * 256 + tid;
        int r = i >> 6, c = i & 63;
        xs[r * XA + c] = __uint_as_float(f2tf32(xs[r * XA + c]));
    }
    __syncthreads();

    int warp = tid >> 5, lane = tid & 31;
    int m0 = (warp & 3) << 4;
    int n0 = (warp >> 2) << 5;
    int g = lane >> 2, tig = lane & 3;
    float acc[4][4];
#pragma unroll
    for (int s = 0; s < 4; s++) { acc[s][0] = acc[s][1] = acc[s][2] = acc[s][3] = 0.f; }
#pragma unroll
    for (int ks = 0; ks < 8; ks++) {
        int k0 = ks << 3;
        unsigned a0 = __float_as_uint(xs[(m0 + g)     * XA + k0 + tig]);
        unsigned a1 = __float_as_uint(xs[(m0 + g + 8) * XA + k0 + tig]);
        unsigned a2 = __float_as_uint(xs[(m0 + g)     * XA + k0 + tig + 4]);
        unsigned a3 = __float_as_uint(xs[(m0 + g + 8) * XA + k0 + tig + 4]);
#pragma unroll
        for (int sub = 0; sub < 4; sub++) {
            int n = n0 + (sub << 3) + g;
            unsigned b0 = __float_as_uint(Ws[(k0 + tig)     * WB + n]);
            unsigned b1 = __float_as_uint(Ws[(k0 + tig + 4) * WB + n]);
            mma_tf32(acc[sub], a0, a1, a2, a3, b0, b1);
        }
    }
    int rlo = m0 + g, rhi = m0 + g + 8;
    int row_lo = row0 + rlo, row_hi = row0 + rhi;
    float s0 = scal[rlo], s1 = scal[rhi];
#pragma unroll
    for (int sub = 0; sub < 4; sub++) {
        int col = n0 + (sub << 3) + (tig << 1);
        if (row_lo < N) {
            __half2 h = __floats2half2_rn(s0 * acc[sub][0], s0 * acc[sub][1]);
            *(__half2*)&hsh[(size_t)row_lo * DD + col] = h;
        }
        if (row_hi < N) {
            __half2 h = __floats2half2_rn(s1 * acc[sub][2], s1 * acc[sub][3]);
            *(__half2*)&hsh[(size_t)row_hi * DD + col] = h;
        }
    }
}

// Fused layer 2: aggregate from hsh (packed CSR gather), relu(b1+dv*a),
// tf32 stage, mma with W2; out = half(dv * (x2@W2)).
__global__ void k_agg_gemm(const __half* __restrict__ hsh,
                           const int* __restrict__ rp, const unsigned* __restrict__ epk,
                           const float* __restrict__ W, const float* __restrict__ b,
                           const float* __restrict__ dg,
                           __half* __restrict__ out, int N) {
    __shared__ float Ws[DD * WB];
    __shared__ float xs[DD * XA];
    __shared__ float dvs[64];
    __shared__ unsigned st[8][32];
    int tid = threadIdx.x;
    int warp = tid >> 5, lane = tid & 31;
    int row0 = blockIdx.x * 64;

#pragma unroll
    for (int it = 0; it < 16; it++) {
        int i = it * 256 + tid;
        Ws[(i >> 6) * WB + (i & 63)] = __uint_as_float(f2tf32(W[i]));
    }
    if (tid < 64) {
        int row = row0 + tid;
        dvs[tid] = (row < N) ? rsqrtf(1.f + dg[row]) : 0.f;
    }
    __syncthreads();

    int c2 = lane << 1;
    float bx = __ldg(&b[c2]), by = __ldg(&b[c2 + 1]);
#pragma unroll
    for (int q = 0; q < 8; q++) {
        int r = (warp << 3) + q;
        int n = row0 + r;
        float vx = 0.f, vy = 0.f;
        if (n < N) {
            float2 a = __half22float2(*(const __half2*)&hsh[(size_t)n * DD + c2]);
            int beg = rp[n], end = rp[n + 1];
            for (int j0 = beg; j0 < end; j0 += 32) {
                int m = end - j0;
                int jl = j0 + ((lane < m) ? lane : (m - 1));
                st[warp][lane] = __ldg(&epk[jl]);
                __syncwarp();
                if (m >= 32) {
#pragma unroll 8
                    for (int k = 0; k < 32; k++) {
                        int s; float w; dec_epk(st[warp][k], s, w);
                        float2 hv = __half22float2(*(const __half2*)&hsh[(size_t)s * DD + c2]);
                        a.x += w * hv.x;
                        a.y += w * hv.y;
                    }
                } else {
                    for (int k = 0; k < m; k++) {
                        int s; float w; dec_epk(st[warp][k], s, w);
                        float2 hv = __half22float2(*(const __half2*)&hsh[(size_t)s * DD + c2]);
                        a.x += w * hv.x;
                        a.y += w * hv.y;
                    }
                }
                __syncwarp();
            }
            float dn = dvs[r];
            vx = fmaxf(bx + dn * a.x, 0.f);
            vy = fmaxf(by + dn * a.y, 0.f);
        }
        xs[r * XA + c2]     = __uint_as_float(f2tf32(vx));
        xs[r * XA + c2 + 1] = __uint_as_float(f2tf32(vy));
    }
    __syncthreads();

    int m0 = (warp & 3) << 4;
    int nb0 = (warp >> 2) << 5;
    int g = lane >> 2, tig = lane & 3;
    float acc[4][4];
#pragma unroll
    for (int s = 0; s < 4; s++) { acc[s][0] = acc[s][1] = acc[s][2] = acc[s][3] = 0.f; }
#pragma unroll
    for (int ks = 0; ks < 8; ks++) {
        int k0 = ks << 3;
        unsigned a0 = __float_as_uint(xs[(m0 + g)     * XA + k0 + tig]);
        unsigned a1 = __float_as_uint(xs[(m0 + g + 8) * XA + k0 + tig]);
        unsigned a2 = __float_as_uint(xs[(m0 + g)     * XA + k0 + tig + 4]);
        unsigned a3 = __float_as_uint(xs[(m0 + g + 8) * XA + k0 + tig + 4]);
#pragma unroll
        for (int sub = 0; sub < 4; sub++) {
            int n = nb0 + (sub << 3) + g;
            unsigned b0 = __float_as_uint(Ws[(k0 + tig)     * WB + n]);
            unsigned b1 = __float_as_uint(Ws[(k0 + tig + 4) * WB + n]);
            mma_tf32(acc[sub], a0, a1, a2, a3, b0, b1);
        }
    }
    int rlo = m0 + g, rhi = m0 + g + 8;
    int row_lo = row0 + rlo, row_hi = row0 + rhi;
    float s0 = dvs[rlo], s1 = dvs[rhi];
#pragma unroll
    for (int sub = 0; sub < 4; sub++) {
        int col = nb0 + (sub << 3) + (tig << 1);
        if (row_lo < N) {
            __half2 h = __floats2half2_rn(s0 * acc[sub][0], s0 * acc[sub][1]);
            *(__half2*)&out[(size_t)row_lo * DD + col] = h;
        }
        if (row_hi < N) {
            __half2 h = __floats2half2_rn(s1 * acc[sub][2], s1 * acc[sub][3]);
            *(__half2*)&out[(size_t)row_hi * DD + col] = h;
        }
    }
}

// Fused layer 3 head: warp per node — aggregate from hsh2, then
// h3s[n] = dv[n] * ( relu(b2 + dv[n]*a) . W3 )
__global__ void k_agg_dot(const __half* __restrict__ hsh2,
                          const int* __restrict__ rp, const unsigned* __restrict__ epk,
                          const float* __restrict__ W3, const float* __restrict__ b2,
                          const float* __restrict__ dg,
                          float* __restrict__ h3s, int N) {
    __shared__ unsigned st[8][32];
    int wid  = threadIdx.x >> 5;
    int lane = threadIdx.x & 31;
    int n = (blockIdx.x * blockDim.x + threadIdx.x) >> 5;
    if (n >= N) return;
    int c2 = lane << 1;
    float2 a = __half22float2(*(const __half2*)&hsh2[(size_t)n * DD + c2]);
    int beg = rp[n], end = rp[n + 1];
    for (int j0 = beg; j0 < end; j0 += 32) {
        int m = end - j0;
        int jl = j0 + ((lane < m) ? lane : (m - 1));
        st[wid][lane] = __ldg(&epk[jl]);
        __syncwarp();
        if (m >= 32) {
#pragma unroll 8
            for (int k = 0; k < 32; k++) {
                int s; float w; dec_epk(st[wid][k], s, w);
                float2 hv = __half22float2(*(const __half2*)&hsh2[(size_t)s * DD + c2]);
                a.x += w * hv.x;
                a.y += w * hv.y;
            }
        } else {
            for (int k = 0; k < m; k++) {
                int s; float w; dec_epk(st[wid][k], s, w);
                float2 hv = __half22float2(*(const __half2*)&hsh2[(size_t)s * DD + c2]);
                a.x += w * hv.x;
                a.y += w * hv.y;
            }
        }
        __syncwarp();
    }
    float d = rsqrtf(1.f + __ldg(&dg[n]));
    float v0 = fmaxf(__ldg(&b2[c2])     + d * a.x, 0.f);
    float v1 = fmaxf(__ldg(&b2[c2 + 1]) + d * a.y, 0.f);
    float s = v0 * __ldg(&W3[c2]) + v1 * __ldg(&W3[c2 + 1]);
#pragma unroll
    for (int o = 16; o > 0; o >>= 1) s += __shfl_xor_sync(0xffffffffu, s, o);
    if (lane == 0) h3s[n] = d * s;
}

// out[n] = b3 + dv[n] * ( h3s[n] + sum w*h3s[src] )   (warp per node)
__global__ void k_agg3(const float* __restrict__ h3s, float* __restrict__ out,
                       const int* __restrict__ rp, const unsigned* __restrict__ epk,
                       const float* __restrict__ b3, const float* __restrict__ dg,
                       int N) {
    int n = (blockIdx.x * blockDim.x + threadIdx.x) >> 5;
    int lane = threadIdx.x & 31;
    if (n >= N) return;
    int beg = rp[n], end = rp[n + 1];
    float t = 0.f;
    for (int j = beg + lane; j < end; j += 32) {
        int s; float w; dec_epk(__ldg(&epk[j]), s, w);
        t += w * __ldg(&h3s[s]);
    }
#pragma unroll
    for (int o = 16; o > 0; o >>= 1) t += __shfl_xor_sync(0xffffffffu, t, o);
    if (lane == 0) {
        float d = rsqrtf(1.f + __ldg(&dg[n]));
        out[n] = __ldg(&b3[0]) + d * (h3s[n] + t);
    }
}

// ---------------- launch ----------------

extern "C" void kernel_launch(void* const* d_in, const int* in_sizes, int n_in,
                              void* d_out, int out_size) {
    const float* feat = (const float*)d_in[0];
    const int*   ei   = (const int*)d_in[1];   // int32 (JAX x64 disabled)
    const float* ev   = (const float*)d_in[2];
    const float* W1   = (const float*)d_in[3];
    const float* b1   = (const float*)d_in[4];
    const float* W2   = (const float*)d_in[5];
    const float* b2   = (const float*)d_in[6];
    const float* W3   = (const float*)d_in[7];
    const float* b3   = (const float*)d_in[8];
    float* out = (float*)d_out;

    int N = in_sizes[0] / DD;
    int E = in_sizes[2];
    const int* src = ei;
    const int* dst = ei + E;

    float *zbuf, *ph3s;
    __half *phsh, *phsh2;
    unsigned* epk;
    int *rp, *cur, *bsum;
    cudaGetSymbolAddress((void**)&zbuf,  g_zbuf);
    cudaGetSymbolAddress((void**)&rp,    g_rp);
    cudaGetSymbolAddress((void**)&cur,   g_cur);
    cudaGetSymbolAddress((void**)&bsum,  g_bsum);
    cudaGetSymbolAddress((void**)&epk,   g_epk);
    cudaGetSymbolAddress((void**)&phsh,  g_hsh);
    cudaGetSymbolAddress((void**)&phsh2, g_hsh2);
    cudaGetSymbolAddress((void**)&ph3s,  g_h3s);

    float* dr = zbuf;            // deg_row
    float* dg = zbuf + NN;       // deg (A_hat col sums into dst)
    int*   cnt = (int*)(zbuf + 2 * NN);

    int nb  = (N + 255) / 256;
    int ebl = (E + 255) / 256;
    int wnb = (N * 32 + 255) / 256;
    int gemm_blocks = (N + 63) / 64;

    // zero dr/dg/cnt in one memset node
    cudaMemsetAsync(zbuf, 0, 3 * NN * sizeof(float), 0);

    // CSR build (+deg fused into scatter)
    k_pre1   <<<ebl, 256>>>(src, dst, ev, dr, cnt, E);
    k_scan1  <<<SCAN_NB, SCAN_BS>>>(cnt, rp, bsum, N);
    k_scan3  <<<nb, 256>>>(rp, cur, bsum, N, E);
    k_scatter<<<ebl, 256>>>(src, dst, ev, dr, dg, cur, epk, E);

    // layer 1: feat -> hsh (rowsum + dinv folded in-kernel)
    k_gemm0   <<<gemm_blocks, 256>>>(feat, W1, dg, phsh, N);
    // layer 2: fused agg(hsh) + relu(b1+dv*a) + GEMM(W2) -> hsh2
    k_agg_gemm<<<gemm_blocks, 256>>>(phsh, rp, epk, W2, b1, dg, phsh2, N);
    // layer 3 head: fused agg(hsh2) + relu(b2+dv*a).W3 -> h3s
    k_agg_dot <<<wnb, 256>>>(phsh2, rp, epk, W3, b2, dg, ph3s, N);
    // final aggregation
    k_agg3    <<<wnb, 256>>>(ph3s, out, rp, epk, b3, dg, N);
}

// round 17
// speedup vs baseline: 1.1390x; 1.0018x over previous
#include <cuda_runtime.h>
#include <cuda_fp16.h>

#define NN 100000
#define EE 1600000
#define DD 64
#define SCAN_BS 1024
#define SCAN_NB ((NN + SCAN_BS - 1) / SCAN_BS)   // 98
#define DEG_SCALE 1048576.f                       // 2^20 fixed-point for deg
#define DEG_INV   (1.f / 1048576.f)

// ---- scratch (static device globals; no allocation anywhere) ----
__device__ float    g_zbuf[2 * NN];            // [dr | cnt], one memset
__device__ unsigned long long g_pk[NN];        // (count<<32) | fixedpoint(deg)
__device__ int      g_rp[NN + 1];              // CSR row_ptr (by dst)
__device__ int      g_bsum[SCAN_NB];           // scan block sums
__device__ unsigned g_epk[EE];                 // CSR: (src<<15) | fp16(w) sans sign
__device__ __align__(16) __half g_hsh[NN * DD];   // fp16: dinv * (x@W1)
__device__ __align__(16) __half g_hsh2[NN * DD];  // fp16: dinv * (x2@W2)
__device__ float g_h3s[NN];

__device__ __forceinline__ float guard1(float v) { return v > 0.f ? v : 1.f; }

__device__ __forceinline__ unsigned f2tf32(float v) {
    unsigned t;
    asm("cvt.rna.tf32.f32 %0, %1;" : "=r"(t) : "f"(v));
    return t;
}

__device__ __forceinline__ void mma_tf32(float* d,
                                         unsigned a0, unsigned a1, unsigned a2, unsigned a3,
                                         unsigned b0, unsigned b1) {
    asm volatile(
        "mma.sync.aligned.m16n8k8.row.col.f32.tf32.tf32.f32 "
        "{%0,%1,%2,%3}, {%4,%5,%6,%7}, {%8,%9}, {%0,%1,%2,%3};"
        : "+f"(d[0]), "+f"(d[1]), "+f"(d[2]), "+f"(d[3])
        : "r"(a0), "r"(a1), "r"(a2), "r"(a3), "r"(b0), "r"(b1));
}

__device__ __forceinline__ void dec_epk(unsigned v, int& s, float& w) {
    s = (int)(v >> 15);
    w = __half2float(__ushort_as_half((unsigned short)(v & 0x7FFFu)));
}

// dv from packed (count | deg_fixed) word
__device__ __forceinline__ float dv_from_pk(unsigned long long pkv) {
    return rsqrtf(1.f + (float)(unsigned)pkv * DEG_INV);
}

// ---------------- precompute ----------------

__global__ void k_pre1(const int* __restrict__ src, const int* __restrict__ dst,
                       const float* __restrict__ ev,
                       float* __restrict__ dr, int* __restrict__ cnt, int E) {
    int e = blockIdx.x * blockDim.x + threadIdx.x;
    if (e >= E) return;
    atomicAdd(&dr[src[e]], ev[e]);
    atomicAdd(&cnt[dst[e]], 1);
}

// block-level exclusive scan of cnt -> rp ; block totals -> bsum (shfl-based)
__global__ void k_scan1(const int* __restrict__ cnt, int* __restrict__ rp,
                        int* __restrict__ bsum, int N) {
    __shared__ int ws[32];
    int t = threadIdx.x;
    int lane = t & 31, wid = t >> 5;
    int i = blockIdx.x * SCAN_BS + t;
    int v = (i < N) ? cnt[i] : 0;
    int x = v;
#pragma unroll
    for (int o = 1; o < 32; o <<= 1) {
        int y = __shfl_up_sync(0xffffffffu, x, o);
        if (lane >= o) x += y;
    }
    if (lane == 31) ws[wid] = x;
    __syncthreads();
    if (wid == 0) {
        int s = ws[lane];
#pragma unroll
        for (int o = 1; o < 32; o <<= 1) {
            int y = __shfl_up_sync(0xffffffffu, s, o);
            if (lane >= o) s += y;
        }
        ws[lane] = s;
    }
    __syncthreads();
    int incl = x + (wid ? ws[wid - 1] : 0);
    if (i < N) rp[i] = incl - v;
    if (t == SCAN_BS - 1) bsum[blockIdx.x] = incl;
}

// rp[i] += prefix(bsum) ; rp[N] = E (redundant per-block scan; no cursor)
__global__ void k_scan3(int* __restrict__ rp, const int* __restrict__ bsum,
                        int N, int E) {
    __shared__ int sh[128];
    int t = threadIdx.x;
    if (t < 128) sh[t] = (t < SCAN_NB) ? bsum[t] : 0;
    __syncthreads();
#pragma unroll
    for (int o = 1; o < 128; o <<= 1) {
        int add = (t >= o && t < 128) ? sh[t - o] : 0;
        __syncthreads();
        if (t < 128) sh[t] += add;
        __syncthreads();
    }
    int i = blockIdx.x * blockDim.x + t;
    if (i >= N) return;
    int blk = i >> 10;
    int off = blk ? sh[blk - 1] : 0;
    rp[i] = rp[i] + off;
    if (i == 0) rp[N] = E;
}

// fused: w_hat + (deg | rank) via ONE packed 64-bit atomic + CSR scatter
__global__ void k_scatter(const int* __restrict__ src, const int* __restrict__ dst,
                          const float* __restrict__ ev, const float* __restrict__ dr,
                          unsigned long long* __restrict__ pk,
                          const int* __restrict__ rp,
                          unsigned* __restrict__ epk, int E) {
    int e = blockIdx.x * blockDim.x + threadIdx.x;
    if (e >= E) return;
    int s = src[e], d = dst[e];
    float w = ev[e] / (guard1(__ldg(&dr[s])) * guard1(__ldg(&dr[d])));
    unsigned fixedw = __float2uint_rn(w * DEG_SCALE);
    unsigned long long ret = atomicAdd(&pk[d], (1ull << 32) | (unsigned long long)fixedw);
    int p = __ldg(&rp[d]) + (int)(ret >> 32);
    unsigned hb = (unsigned)__half_as_ushort(__float2half_rn(w));  // w>0: bit15=0
    epk[p] = ((unsigned)s << 15) | hb;
}

// ---------------- layers ----------------

#define XA 68   // xs stride: conflict-free A-frag loads
#define WB 72   // Ws stride: conflict-free B-frag loads

// Layer 1 GEMM: hsh[row,c] = half( (dv[row]/rowsum(feat[row])) * (feat@W1)[c] )
__global__ void k_gemm0(const float* __restrict__ in, const float* __restrict__ W,
                        const unsigned long long* __restrict__ pk,
                        __half* __restrict__ hsh, int N) {
    __shared__ float Ws[DD * WB];
    __shared__ float xs[DD * XA];
    __shared__ float scal[64];
    int tid = threadIdx.x;
    int row0 = blockIdx.x * 64;

#pragma unroll
    for (int it = 0; it < 16; it++) {
        int i = it * 256 + tid;
        Ws[(i >> 6) * WB + (i & 63)] = __uint_as_float(f2tf32(W[i]));
    }
    // stage raw feat
#pragma unroll
    for (int it = 0; it < 16; it++) {
        int i = it * 256 + tid;
        int r = i >> 6, c = i & 63;
        int row = row0 + r;
        xs[r * XA + c] = (row < N) ? in[(size_t)row * DD + c] : 0.f;
    }
    __syncthreads();
    // per-row sums -> scal = dv/rowsum  (dv decoded from pk)
    if (tid < 64) {
        int row = row0 + tid;
        float s = 0.f;
        const float* xr = &xs[tid * XA];
#pragma unroll
        for (int c = 0; c < DD; c++) s += xr[c];
        float dv = (row < N) ? dv_from_pk(pk[row]) : 0.f;
        scal[tid] = dv / fmaxf(s, 1e-30f);
    }
    __syncthreads();
    // cvt staged tile to tf32 in place
#pragma unroll
    for (int it = 0; it < 16; it++) {
        int i = it * 256 + tid;
        int r = i >> 6, c = i & 63;
        xs[r * XA + c] = __uint_as_float(f2tf32(xs[r * XA + c]));
    }
    __syncthreads();

    int warp = tid >> 5, lane = tid & 31;
    int m0 = (warp & 3) << 4;
    int n0 = (warp >> 2) << 5;
    int g = lane >> 2, tig = lane & 3;
    float acc[4][4];
#pragma unroll
    for (int s = 0; s < 4; s++) { acc[s][0] = acc[s][1] = acc[s][2] = acc[s][3] = 0.f; }
#pragma unroll
    for (int ks = 0; ks < 8; ks++) {
        int k0 = ks << 3;
        unsigned a0 = __float_as_uint(xs[(m0 + g)     * XA + k0 + tig]);
        unsigned a1 = __float_as_uint(xs[(m0 + g + 8) * XA + k0 + tig]);
        unsigned a2 = __float_as_uint(xs[(m0 + g)     * XA + k0 + tig + 4]);
        unsigned a3 = __float_as_uint(xs[(m0 + g + 8) * XA + k0 + tig + 4]);
#pragma unroll
        for (int sub = 0; sub < 4; sub++) {
            int n = n0 + (sub << 3) + g;
            unsigned b0 = __float_as_uint(Ws[(k0 + tig)     * WB + n]);
            unsigned b1 = __float_as_uint(Ws[(k0 + tig + 4) * WB + n]);
            mma_tf32(acc[sub], a0, a1, a2, a3, b0, b1);
        }
    }
    int rlo = m0 + g, rhi = m0 + g + 8;
    int row_lo = row0 + rlo, row_hi = row0 + rhi;
    float s0 = scal[rlo], s1 = scal[rhi];
#pragma unroll
    for (int sub = 0; sub < 4; sub++) {
        int col = n0 + (sub << 3) + (tig << 1);
        if (row_lo < N) {
            __half2 h = __floats2half2_rn(s0 * acc[sub][0], s0 * acc[sub][1]);
            *(__half2*)&hsh[(size_t)row_lo * DD + col] = h;
        }
        if (row_hi < N) {
            __half2 h = __floats2half2_rn(s1 * acc[sub][2], s1 * acc[sub][3]);
            *(__half2*)&hsh[(size_t)row_hi * DD + col] = h;
        }
    }
}

// Fused layer 2 (FROZEN R8 agg loop): aggregate from hsh, relu(b1+dv*a),
// tf32 stage, mma with W2; out = half(dv * (x2@W2)).
__global__ void k_agg_gemm(const __half* __restrict__ hsh,
                           const int* __restrict__ rp, const unsigned* __restrict__ epk,
                           const float* __restrict__ W, const float* __restrict__ b,
                           const unsigned long long* __restrict__ pk,
                           __half* __restrict__ out, int N) {
    __shared__ float Ws[DD * WB];
    __shared__ float xs[DD * XA];
    __shared__ float dvs[64];
    __shared__ unsigned st[8][32];
    int tid = threadIdx.x;
    int warp = tid >> 5, lane = tid & 31;
    int row0 = blockIdx.x * 64;

#pragma unroll
    for (int it = 0; it < 16; it++) {
        int i = it * 256 + tid;
        Ws[(i >> 6) * WB + (i & 63)] = __uint_as_float(f2tf32(W[i]));
    }
    if (tid < 64) {
        int row = row0 + tid;
        dvs[tid] = (row < N) ? dv_from_pk(pk[row]) : 0.f;
    }
    __syncthreads();

    int c2 = lane << 1;
    float bx = __ldg(&b[c2]), by = __ldg(&b[c2 + 1]);
#pragma unroll
    for (int q = 0; q < 8; q++) {
        int r = (warp << 3) + q;
        int n = row0 + r;
        float vx = 0.f, vy = 0.f;
        if (n < N) {
            float2 a = __half22float2(*(const __half2*)&hsh[(size_t)n * DD + c2]);
            int beg = rp[n], end = rp[n + 1];
            for (int j0 = beg; j0 < end; j0 += 32) {
                int m = end - j0;
                int jl = j0 + ((lane < m) ? lane : (m - 1));
                st[warp][lane] = __ldg(&epk[jl]);
                __syncwarp();
                if (m >= 32) {
#pragma unroll 8
                    for (int k = 0; k < 32; k++) {
                        int s; float w; dec_epk(st[warp][k], s, w);
                        float2 hv = __half22float2(*(const __half2*)&hsh[(size_t)s * DD + c2]);
                        a.x += w * hv.x;
                        a.y += w * hv.y;
                    }
                } else {
                    for (int k = 0; k < m; k++) {
                        int s; float w; dec_epk(st[warp][k], s, w);
                        float2 hv = __half22float2(*(const __half2*)&hsh[(size_t)s * DD + c2]);
                        a.x += w * hv.x;
                        a.y += w * hv.y;
                    }
                }
                __syncwarp();
            }
            float dn = dvs[r];
            vx = fmaxf(bx + dn * a.x, 0.f);
            vy = fmaxf(by + dn * a.y, 0.f);
        }
        xs[r * XA + c2]     = __uint_as_float(f2tf32(vx));
        xs[r * XA + c2 + 1] = __uint_as_float(f2tf32(vy));
    }
    __syncthreads();

    int m0 = (warp & 3) << 4;
    int nb0 = (warp >> 2) << 5;
    int g = lane >> 2, tig = lane & 3;
    float acc[4][4];
#pragma unroll
    for (int s = 0; s < 4; s++) { acc[s][0] = acc[s][1] = acc[s][2] = acc[s][3] = 0.f; }
#pragma unroll
    for (int ks = 0; ks < 8; ks++) {
        int k0 = ks << 3;
        unsigned a0 = __float_as_uint(xs[(m0 + g)     * XA + k0 + tig]);
        unsigned a1 = __float_as_uint(xs[(m0 + g + 8) * XA + k0 + tig]);
        unsigned a2 = __float_as_uint(xs[(m0 + g)     * XA + k0 + tig + 4]);
        unsigned a3 = __float_as_uint(xs[(m0 + g + 8) * XA + k0 + tig + 4]);
#pragma unroll
        for (int sub = 0; sub < 4; sub++) {
            int n = nb0 + (sub << 3) + g;
            unsigned b0 = __float_as_uint(Ws[(k0 + tig)     * WB + n]);
            unsigned b1 = __float_as_uint(Ws[(k0 + tig + 4) * WB + n]);
            mma_tf32(acc[sub], a0, a1, a2, a3, b0, b1);
        }
    }
    int rlo = m0 + g, rhi = m0 + g + 8;
    int row_lo = row0 + rlo, row_hi = row0 + rhi;
    float s0 = dvs[rlo], s1 = dvs[rhi];
#pragma unroll
    for (int sub = 0; sub < 4; sub++) {
        int col = nb0 + (sub << 3) + (tig << 1);
        if (row_lo < N) {
            __half2 h = __floats2half2_rn(s0 * acc[sub][0], s0 * acc[sub][1]);
            *(__half2*)&out[(size_t)row_lo * DD + col] = h;
        }
        if (row_hi < N) {
            __half2 h = __floats2half2_rn(s1 * acc[sub][2], s1 * acc[sub][3]);
            *(__half2*)&out[(size_t)row_hi * DD + col] = h;
        }
    }
}

// Fused layer 3 head (FROZEN warp-per-node agg): aggregate from hsh2, then
// h3s[n] = dv[n] * ( relu(b2 + dv[n]*a) . W3 )
__global__ void k_agg_dot(const __half* __restrict__ hsh2,
                          const int* __restrict__ rp, const unsigned* __restrict__ epk,
                          const float* __restrict__ W3, const float* __restrict__ b2,
                          const unsigned long long* __restrict__ pk,
                          float* __restrict__ h3s, int N) {
    __shared__ unsigned st[8][32];
    int wid  = threadIdx.x >> 5;
    int lane = threadIdx.x & 31;
    int n = (blockIdx.x * blockDim.x + threadIdx.x) >> 5;
    if (n >= N) return;
    int c2 = lane << 1;
    float2 a = __half22float2(*(const __half2*)&hsh2[(size_t)n * DD + c2]);
    int beg = rp[n], end = rp[n + 1];
    for (int j0 = beg; j0 < end; j0 += 32) {
        int m = end - j0;
        int jl = j0 + ((lane < m) ? lane : (m - 1));
        st[wid][lane] = __ldg(&epk[jl]);
        __syncwarp();
        if (m >= 32) {
#pragma unroll 8
            for (int k = 0; k < 32; k++) {
                int s; float w; dec_epk(st[wid][k], s, w);
                float2 hv = __half22float2(*(const __half2*)&hsh2[(size_t)s * DD + c2]);
                a.x += w * hv.x;
                a.y += w * hv.y;
            }
        } else {
            for (int k = 0; k < m; k++) {
                int s; float w; dec_epk(st[wid][k], s, w);
                float2 hv = __half22float2(*(const __half2*)&hsh2[(size_t)s * DD + c2]);
                a.x += w * hv.x;
                a.y += w * hv.y;
            }
        }
        __syncwarp();
    }
    float d = dv_from_pk(__ldg(&pk[n]));
    float v0 = fmaxf(__ldg(&b2[c2])     + d * a.x, 0.f);
    float v1 = fmaxf(__ldg(&b2[c2 + 1]) + d * a.y, 0.f);
    float s = v0 * __ldg(&W3[c2]) + v1 * __ldg(&W3[c2 + 1]);
#pragma unroll
    for (int o = 16; o > 0; o >>= 1) s += __shfl_xor_sync(0xffffffffu, s, o);
    if (lane == 0) h3s[n] = d * s;
}

// out[n] = b3 + dv[n] * ( h3s[n] + sum w*h3s[src] )   (warp per node)
__global__ void k_agg3(const float* __restrict__ h3s, float* __restrict__ out,
                       const int* __restrict__ rp, const unsigned* __restrict__ epk,
                       const float* __restrict__ b3,
                       const unsigned long long* __restrict__ pk,
                       int N) {
    int n = (blockIdx.x * blockDim.x + threadIdx.x) >> 5;
    int lane = threadIdx.x & 31;
    if (n >= N) return;
    int beg = rp[n], end = rp[n + 1];
    float t = 0.f;
    for (int j = beg + lane; j < end; j += 32) {
        int s; float w; dec_epk(__ldg(&epk[j]), s, w);
        t += w * __ldg(&h3s[s]);
    }
#pragma unroll
    for (int o = 16; o > 0; o >>= 1) t += __shfl_xor_sync(0xffffffffu, t, o);
    if (lane == 0) {
        float d = dv_from_pk(__ldg(&pk[n]));
        out[n] = __ldg(&b3[0]) + d * (h3s[n] + t);
    }
}

// ---------------- launch ----------------

extern "C" void kernel_launch(void* const* d_in, const int* in_sizes, int n_in,
                              void* d_out, int out_size) {
    const float* feat = (const float*)d_in[0];
    const int*   ei   = (const int*)d_in[1];   // int32 (JAX x64 disabled)
    const float* ev   = (const float*)d_in[2];
    const float* W1   = (const float*)d_in[3];
    const float* b1   = (const float*)d_in[4];
    const float* W2   = (const float*)d_in[5];
    const float* b2   = (const float*)d_in[6];
    const float* W3   = (const float*)d_in[7];
    const float* b3   = (const float*)d_in[8];
    float* out = (float*)d_out;

    int N = in_sizes[0] / DD;
    int E = in_sizes[2];
    const int* src = ei;
    const int* dst = ei + E;

    float *zbuf, *ph3s;
    unsigned long long* pk;
    __half *phsh, *phsh2;
    unsigned* epk;
    int *rp, *bsum;
    cudaGetSymbolAddress((void**)&zbuf,  g_zbuf);
    cudaGetSymbolAddress((void**)&pk,    g_pk);
    cudaGetSymbolAddress((void**)&rp,    g_rp);
    cudaGetSymbolAddress((void**)&bsum,  g_bsum);
    cudaGetSymbolAddress((void**)&epk,   g_epk);
    cudaGetSymbolAddress((void**)&phsh,  g_hsh);
    cudaGetSymbolAddress((void**)&phsh2, g_hsh2);
    cudaGetSymbolAddress((void**)&ph3s,  g_h3s);

    float* dr  = zbuf;                 // deg_row
    int*   cnt = (int*)(zbuf + NN);    // dst histogram

    int nb  = (N + 255) / 256;
    int ebl = (E + 255) / 256;
    int wnb = (N * 32 + 255) / 256;
    int gemm_blocks = (N + 63) / 64;

    cudaMemsetAsync(zbuf, 0, 2 * NN * sizeof(float), 0);
    cudaMemsetAsync(pk,   0, NN * sizeof(unsigned long long), 0);

    // CSR build: deg+rank via single packed 64-bit atomic in scatter
    k_pre1   <<<ebl, 256>>>(src, dst, ev, dr, cnt, E);
    k_scan1  <<<SCAN_NB, SCAN_BS>>>(cnt, rp, bsum, N);
    k_scan3  <<<nb, 256>>>(rp, bsum, N, E);
    k_scatter<<<ebl, 256>>>(src, dst, ev, dr, pk, rp, epk, E);

    // layer 1: feat -> hsh (rowsum + dinv folded in-kernel)
    k_gemm0   <<<gemm_blocks, 256>>>(feat, W1, pk, phsh, N);
    // layer 2: fused agg(hsh) + relu(b1+dv*a) + GEMM(W2) -> hsh2
    k_agg_gemm<<<gemm_blocks, 256>>>(phsh, rp, epk, W2, b1, pk, phsh2, N);
    // layer 3 head: fused agg(hsh2) + relu(b2+dv*a).W3 -> h3s
    k_agg_dot <<<wnb, 256>>>(phsh2, rp, epk, W3, b2, pk, ph3s, N);
    // final aggregation
    k_agg3    <<<wnb, 256>>>(ph3s, out, rp, epk, b3, pk, N);
}